// round 16
// baseline (speedup 1.0000x reference)
#include <cuda_runtime.h>
#include <cuda_bf16.h>
#include <cuda_fp16.h>
#include <cstdint>

#define N 8192
#define F 128
#define CSRW 128        // fixed CSR row width; max in-degree ~60 for Binomial(8192, 32/8192)
#define GEMM_ROWS 16    // rows per fused gemm1 block
#define GEMM_GRID (N / GEMM_ROWS)   // 512
#define XS_STRIDE 18
#define BP 136          // hgemm smem pitch in halves (conflict-free ldmatrix)

// ---------------- scratch (static device globals; no allocation) ----------
__device__ __half g_Z[N * F];       // GEMM output, fp16; dis_j-scaled before SpMM
__device__ __half g_H1[N * F];      // layer-1 activation, fp16 (hgemm input)
__device__ __half g_W2h[F * F];     // W2 in fp16 [k][n]
__device__ int    g_cnt[N];         // in-degree per dst
__device__ float  g_dis[N];         // D^{-1/2} table
__device__ int    g_csr[N * CSRW];  // fixed-slot CSR

// ---------------- f32x2 packed helpers ------------------------------------
__device__ __forceinline__ uint64_t pk2(float lo, float hi) {
    uint64_t r;
    asm("mov.b64 %0, {%1, %2};" : "=l"(r) : "f"(lo), "f"(hi));
    return r;
}
__device__ __forceinline__ uint64_t fma2(uint64_t a, uint64_t b, uint64_t c) {
    uint64_t d;
    asm("fma.rn.f32x2 %0, %1, %2, %3;" : "=l"(d) : "l"(a), "l"(b), "l"(c));
    return d;
}
__device__ __forceinline__ uint64_t add2(uint64_t a, uint64_t b) {
    uint64_t d;
    asm("add.rn.f32x2 %0, %1, %2;" : "=l"(d) : "l"(a), "l"(b));
    return d;
}
__device__ __forceinline__ void upk2(uint64_t v, float& lo, float& hi) {
    asm("mov.b64 {%0, %1}, %2;" : "=f"(lo), "=f"(hi) : "l"(v));
}

// -------- scalar gemm body for layer 1 (fused under extract; fp16 out) -----
__device__ __forceinline__ void gemm_body_h(const float* __restrict__ M,
                                            const float* __restrict__ W,
                                            __half* __restrict__ out,
                                            int rowBase, int tid,
                                            float* Xs) {
    #pragma unroll
    for (int it = 0; it < 8; it++) {
        int idx = tid + 256 * it;
        int r = idx >> 7;
        int k = idx & 127;
        Xs[k * XS_STRIDE + r] = M[(rowBase + r) * F + k];
    }
    __syncthreads();

    const float4* W4 = (const float4*)W;
    int cg = tid & 31;
    int rp = tid >> 5;

    uint64_t acc[4];
    #pragma unroll
    for (int c = 0; c < 4; c++) acc[c] = 0;

    float4 w = W4[cg];
    #pragma unroll 8
    for (int k = 0; k < 128; k++) {
        float4 wc = w;
        if (k < 127) w = W4[(k + 1) * 32 + cg];
        uint64_t xp = *(const uint64_t*)&Xs[k * XS_STRIDE + 2 * rp];
        acc[0] = fma2(xp, pk2(wc.x, wc.x), acc[0]);
        acc[1] = fma2(xp, pk2(wc.y, wc.y), acc[1]);
        acc[2] = fma2(xp, pk2(wc.z, wc.z), acc[2]);
        acc[3] = fma2(xp, pk2(wc.w, wc.w), acc[3]);
    }

    float lo[4], hi[4];
    #pragma unroll
    for (int c = 0; c < 4; c++) upk2(acc[c], lo[c], hi[c]);

    uint2* out2 = (uint2*)out;
    int rowA = rowBase + 2 * rp;
    __half2 a01 = __floats2half2_rn(lo[0], lo[1]);
    __half2 a23 = __floats2half2_rn(lo[2], lo[3]);
    __half2 b01 = __floats2half2_rn(hi[0], hi[1]);
    __half2 b23 = __floats2half2_rn(hi[2], hi[3]);
    uint2 va, vb;
    va.x = *(uint32_t*)&a01; va.y = *(uint32_t*)&a23;
    vb.x = *(uint32_t*)&b01; vb.y = *(uint32_t*)&b23;
    out2[rowA * 32 + cg]       = va;
    out2[(rowA + 1) * 32 + cg] = vb;
}

// -------- extract body: register-batched loads + integer tests -------------
__device__ __forceinline__ void extract_body(const float* __restrict__ A,
                                             int bid, int tid) {
    const uint4* A4 = (const uint4*)A;
    int base = bid * 2048 + tid;
    uint4 u[8];
    #pragma unroll
    for (int s = 0; s < 8; s++) u[s] = __ldcs(A4 + base + 256 * s);  // MLP=8
    #pragma unroll
    for (int s = 0; s < 8; s++) {
        if (u[s].x | u[s].y | u[s].z | u[s].w) {   // A is exactly 0.0f/1.0f
            int idx0 = (base + 256 * s) * 4;
            uint32_t w[4] = {u[s].x, u[s].y, u[s].z, u[s].w};
            #pragma unroll
            for (int c = 0; c < 4; c++) {
                if (w[c]) {
                    int idx = idx0 + c;
                    int i = idx & (N - 1);   // col = dst
                    int j = idx >> 13;       // row = src
                    int p = atomicAdd(&g_cnt[i], 1);
                    if (p < CSRW) g_csr[i * CSRW + p] = j;
                }
            }
        }
    }
}

// ------- fused: scalar gemm1 (blocks 0..511, FIRST) + extract --------------
__global__ void __launch_bounds__(256)
fused_extract_gemm_kernel(const float* __restrict__ A,
                          const float* __restrict__ X,
                          const float* __restrict__ W1,
                          __half* __restrict__ Z) {
    __shared__ float Xs[128 * XS_STRIDE];
    int b = blockIdx.x;
    if (b < GEMM_GRID) {
        gemm_body_h(X, W1, Z, b * GEMM_ROWS, threadIdx.x, Xs);
    } else {
        extract_body(A, b - GEMM_GRID, threadIdx.x);
    }
}

// -------- prep_pre: zero g_cnt + W2 -> fp16 (runs FIRST) -------------------
__global__ void __launch_bounds__(256)
prep_pre_kernel(const float* __restrict__ W2) {
    int b = blockIdx.x, tid = threadIdx.x;
    if (b < 16) {                    // W2: 4096 float4
        int q = b * 256 + tid;
        float4 v = ((const float4*)W2)[q];
        __half2 h01 = __floats2half2_rn(v.x, v.y);
        __half2 h23 = __floats2half2_rn(v.z, v.w);
        uint2 u;
        u.x = *(uint32_t*)&h01; u.y = *(uint32_t*)&h23;
        ((uint2*)g_W2h)[q] = u;
    } else {                         // zero g_cnt: 2048 int4
        ((int4*)g_cnt)[(b - 16) * 256 + tid] = make_int4(0, 0, 0, 0);
    }
}

// ---- dis_scale: build g_dis AND scale layer-1 Z in place by dis_row -------
__global__ void __launch_bounds__(256)
dis_scale_kernel() {
    int q = blockIdx.x * 256 + threadIdx.x;  // grid 512: 131072 uint4 (8 halves)
    int r = q >> 4;                          // row (16 uint4 per row)
    float d = rsqrtf((float)g_cnt[r] + 1.0f);
    if ((q & 15) == 0) g_dis[r] = d;
    uint4 v = ((const uint4*)g_Z)[q];
    uint32_t* h = (uint32_t*)&v;
    #pragma unroll
    for (int j = 0; j < 4; j++) {
        float2 f = __half22float2(*(const __half2*)&h[j]);
        __half2 s = __floats2half2_rn(f.x * d, f.y * d);
        h[j] = *(uint32_t*)&s;
    }
    ((uint4*)g_Z)[q] = v;
}

// -------- HMMA gemm2: grid 512, 128 thr, block tile 16x128, warp 16x32 -----
// Epilogue scales by g_dis[row] (Z must be dis-scaled for spmm2).
__global__ void __launch_bounds__(128)
hgemm_kernel(const __half* __restrict__ Ag,   // [N,128] fp16
             __half* __restrict__ outg) {     // [N,128] fp16, dis-scaled
    __shared__ __align__(16) __half As[16 * BP];
    __shared__ __align__(16) __half Bs[128 * BP];
    int tid = threadIdx.x;
    int rowBase = blockIdx.x * 16;

    const uint4* A4 = (const uint4*)(Ag + rowBase * F);
    #pragma unroll
    for (int it = 0; it < 2; it++) {
        int idx = tid + 128 * it;
        int r = idx >> 4, c8 = idx & 15;
        *(uint4*)&As[r * BP + c8 * 8] = A4[idx];
    }
    const uint4* B4 = (const uint4*)g_W2h;
    #pragma unroll
    for (int it = 0; it < 16; it++) {
        int idx = tid + 128 * it;
        int r = idx >> 4, c8 = idx & 15;
        *(uint4*)&Bs[r * BP + c8 * 8] = B4[idx];
    }
    __syncthreads();

    int warp = tid >> 5, lane = tid & 31;
    int n0 = warp * 32;

    float c[4][4];
    #pragma unroll
    for (int nb = 0; nb < 4; nb++)
        #pragma unroll
        for (int q = 0; q < 4; q++) c[nb][q] = 0.0f;

    unsigned aBase = (unsigned)__cvta_generic_to_shared(As);
    unsigned bBase = (unsigned)__cvta_generic_to_shared(Bs);
    int lr = lane & 15, lc = lane >> 4;

    #pragma unroll
    for (int kc = 0; kc < 8; kc++) {
        uint32_t a[4];
        {
            unsigned addr = aBase + ((lr * BP + kc * 16 + lc * 8) << 1);
            asm volatile("ldmatrix.sync.aligned.m8n8.x4.shared.b16 {%0,%1,%2,%3}, [%4];"
                         : "=r"(a[0]), "=r"(a[1]), "=r"(a[2]), "=r"(a[3])
                         : "r"(addr));
        }
        uint32_t b[2][4];
        #pragma unroll
        for (int nt = 0; nt < 2; nt++) {
            unsigned addr = bBase + (((kc * 16 + lr) * BP + n0 + nt * 16 + lc * 8) << 1);
            asm volatile("ldmatrix.sync.aligned.m8n8.x4.trans.shared.b16 {%0,%1,%2,%3}, [%4];"
                         : "=r"(b[nt][0]), "=r"(b[nt][1]), "=r"(b[nt][2]), "=r"(b[nt][3])
                         : "r"(addr));
        }
        #pragma unroll
        for (int nb = 0; nb < 4; nb++) {
            uint32_t b0 = b[nb >> 1][(nb & 1) * 2];
            uint32_t b1 = b[nb >> 1][(nb & 1) * 2 + 1];
            asm volatile(
                "mma.sync.aligned.m16n8k16.row.col.f32.f16.f16.f32 "
                "{%0,%1,%2,%3}, {%4,%5,%6,%7}, {%8,%9}, {%0,%1,%2,%3};"
                : "+f"(c[nb][0]), "+f"(c[nb][1]), "+f"(c[nb][2]), "+f"(c[nb][3])
                : "r"(a[0]), "r"(a[1]), "r"(a[2]), "r"(a[3]),
                  "r"(b0), "r"(b1));
        }
    }

    __half2* O2 = (__half2*)outg;
    int fr = lane >> 2, fc = lane & 3;
    int row0 = rowBase + fr;
    int row1 = row0 + 8;
    float d0 = g_dis[row0];
    float d1 = g_dis[row1];
    #pragma unroll
    for (int nb = 0; nb < 4; nb++) {
        int col2 = (n0 + nb * 8 + 2 * fc) >> 1;
        O2[row0 * 64 + col2] = __floats2half2_rn(c[nb][0] * d0, c[nb][1] * d0);
        O2[row1 * 64 + col2] = __floats2half2_rn(c[nb][2] * d1, c[nb][3] * d1);
    }
}

// ---- SpMM v5: one warp per dst row; double-buffered 8-wide load batches ---
// Z pre-scaled by dis_j. out[i,:] = relu(dis_i*(Zs[i,:]+sum Zs[j,:]) + b)
template<bool HOUT>
__global__ void __launch_bounds__(256)
spmm_kernel(const __half* __restrict__ Z,
            const float* __restrict__ bias,
            void* __restrict__ outv) {
    __shared__ int sidx[8][CSRW];
    int warp = threadIdx.x >> 5;
    int lane = threadIdx.x & 31;
    int i = blockIdx.x * 8 + warp;

    int cnt = g_cnt[i];
    int m = cnt < CSRW ? cnt : CSRW;

    for (int e = lane; e < m; e += 32)
        sidx[warp][e] = g_csr[i * CSRW + e] * 32;
    __syncwarp();

    const uint2* Z2 = (const uint2*)Z;
    float dis_i = g_dis[i];

    uint2 self = Z2[i * 32 + lane];   // already dis_i-scaled
    float2 sa = __half22float2(*(const __half2*)&self.x);
    float2 sb = __half22float2(*(const __half2*)&self.y);
    uint64_t acc0 = pk2(sa.x, sa.y);
    uint64_t acc1 = pk2(sb.x, sb.y);

    int mm = m & ~7;                  // full 8-batches
    if (mm) {
        uint2 cur[8];
        #pragma unroll
        for (int q = 0; q < 8; q++) cur[q] = Z2[sidx[warp][q] + lane];
        for (int e = 8; e < mm; e += 8) {
            uint2 nxt[8];
            #pragma unroll
            for (int q = 0; q < 8; q++) nxt[q] = Z2[sidx[warp][e + q] + lane];
            #pragma unroll
            for (int q = 0; q < 8; q++) {
                float2 fa = __half22float2(*(const __half2*)&cur[q].x);
                float2 fb = __half22float2(*(const __half2*)&cur[q].y);
                acc0 = add2(acc0, pk2(fa.x, fa.y));
                acc1 = add2(acc1, pk2(fb.x, fb.y));
            }
            #pragma unroll
            for (int q = 0; q < 8; q++) cur[q] = nxt[q];
        }
        #pragma unroll
        for (int q = 0; q < 8; q++) {
            float2 fa = __half22float2(*(const __half2*)&cur[q].x);
            float2 fb = __half22float2(*(const __half2*)&cur[q].y);
            acc0 = add2(acc0, pk2(fa.x, fa.y));
            acc1 = add2(acc1, pk2(fb.x, fb.y));
        }
    }
    for (int e = mm; e < m; e++) {
        uint2 u = Z2[sidx[warp][e] + lane];
        float2 fa = __half22float2(*(const __half2*)&u.x);
        float2 fb = __half22float2(*(const __half2*)&u.y);
        acc0 = add2(acc0, pk2(fa.x, fa.y));
        acc1 = add2(acc1, pk2(fb.x, fb.y));
    }

    float a0, a1, a2, a3;
    upk2(acc0, a0, a1);
    upk2(acc1, a2, a3);
    float4 b4 = ((const float4*)bias)[lane];
    float r0 = fmaxf(dis_i * a0 + b4.x, 0.0f);
    float r1 = fmaxf(dis_i * a1 + b4.y, 0.0f);
    float r2 = fmaxf(dis_i * a2 + b4.z, 0.0f);
    float r3 = fmaxf(dis_i * a3 + b4.w, 0.0f);

    if (HOUT) {
        __half2 h01 = __floats2half2_rn(r0, r1);
        __half2 h23 = __floats2half2_rn(r2, r3);
        uint2 v;
        v.x = *(uint32_t*)&h01; v.y = *(uint32_t*)&h23;
        ((uint2*)outv)[i * 32 + lane] = v;
    } else {
        ((float4*)outv)[i * 32 + lane] = make_float4(r0, r1, r2, r3);
    }
}

// ---------------- launch ---------------------------------------------------
extern "C" void kernel_launch(void* const* d_in, const int* in_sizes, int n_in,
                              void* d_out, int out_size) {
    const float* X  = (const float*)d_in[0];
    const float* A  = (const float*)d_in[1];
    const float* W1 = (const float*)d_in[2];
    const float* b1 = (const float*)d_in[3];
    const float* W2 = (const float*)d_in[4];
    const float* b2 = (const float*)d_in[5];
    float* out = (float*)d_out;

    __half* Z;  cudaGetSymbolAddress((void**)&Z,  g_Z);
    __half* H1; cudaGetSymbolAddress((void**)&H1, g_H1);

    prep_pre_kernel<<<24, 256>>>(W2);               // zero cnt + W2 fp16

    // scalar gemm1 (blocks 0..511, start immediately) + extract CSR (8192 blocks)
    fused_extract_gemm_kernel<<<GEMM_GRID + 8192, 256>>>(A, X, W1, Z);
    dis_scale_kernel<<<512, 256>>>();               // g_dis + Z *= dis_row

    spmm_kernel<true ><<<1024, 256>>>(Z, b1, H1);   // H1 = relu(An@(X@W1)+b1), fp16
    hgemm_kernel<<<512, 128>>>(H1, Z);              // Z = dis .* (H1 @ W2)  (HMMA)
    spmm_kernel<false><<<1024, 256>>>(Z, b2, out);  // out = relu(An@(H1@W2)+b2)
}

// round 17
// speedup vs baseline: 1.0375x; 1.0375x over previous
#include <cuda_runtime.h>
#include <cuda_bf16.h>
#include <cuda_fp16.h>
#include <cstdint>

#define N 8192
#define F 128
#define CSRW 128        // fixed CSR row width; max in-degree ~60 for Binomial(8192, 32/8192)
#define GEMM_ROWS 16    // rows per fused gemm1 block
#define GEMM_GRID (N / GEMM_ROWS)   // 512
#define XS_STRIDE 18
#define BP 136          // hgemm smem pitch in halves (conflict-free ldmatrix)

// ---------------- scratch (static device globals; no allocation) ----------
__device__ __half g_Z[N * F];       // GEMM output, fp16; dis_j-scaled before SpMM
__device__ __half g_H1[N * F];      // layer-1 activation, fp16 (hgemm input)
__device__ __half g_W2h[F * F];     // W2 in fp16 [k][n]
__device__ int    g_cnt[N];         // in-degree per dst
__device__ float  g_dis[N];         // D^{-1/2} table
__device__ int    g_csr[N * CSRW];  // fixed-slot CSR

// ---------------- f32x2 packed helpers ------------------------------------
__device__ __forceinline__ uint64_t pk2(float lo, float hi) {
    uint64_t r;
    asm("mov.b64 %0, {%1, %2};" : "=l"(r) : "f"(lo), "f"(hi));
    return r;
}
__device__ __forceinline__ uint64_t fma2(uint64_t a, uint64_t b, uint64_t c) {
    uint64_t d;
    asm("fma.rn.f32x2 %0, %1, %2, %3;" : "=l"(d) : "l"(a), "l"(b), "l"(c));
    return d;
}
__device__ __forceinline__ uint64_t add2(uint64_t a, uint64_t b) {
    uint64_t d;
    asm("add.rn.f32x2 %0, %1, %2;" : "=l"(d) : "l"(a), "l"(b));
    return d;
}
__device__ __forceinline__ void upk2(uint64_t v, float& lo, float& hi) {
    asm("mov.b64 {%0, %1}, %2;" : "=f"(lo), "=f"(hi) : "l"(v));
}

// -------- scalar gemm body for layer 1 (fused under extract; fp16 out) -----
__device__ __forceinline__ void gemm_body_h(const float* __restrict__ M,
                                            const float* __restrict__ W,
                                            __half* __restrict__ out,
                                            int rowBase, int tid,
                                            float* Xs) {
    #pragma unroll
    for (int it = 0; it < 8; it++) {
        int idx = tid + 256 * it;
        int r = idx >> 7;
        int k = idx & 127;
        Xs[k * XS_STRIDE + r] = M[(rowBase + r) * F + k];
    }
    __syncthreads();

    const float4* W4 = (const float4*)W;
    int cg = tid & 31;
    int rp = tid >> 5;

    uint64_t acc[4];
    #pragma unroll
    for (int c = 0; c < 4; c++) acc[c] = 0;

    float4 w = W4[cg];
    #pragma unroll 8
    for (int k = 0; k < 128; k++) {
        float4 wc = w;
        if (k < 127) w = W4[(k + 1) * 32 + cg];
        uint64_t xp = *(const uint64_t*)&Xs[k * XS_STRIDE + 2 * rp];
        acc[0] = fma2(xp, pk2(wc.x, wc.x), acc[0]);
        acc[1] = fma2(xp, pk2(wc.y, wc.y), acc[1]);
        acc[2] = fma2(xp, pk2(wc.z, wc.z), acc[2]);
        acc[3] = fma2(xp, pk2(wc.w, wc.w), acc[3]);
    }

    float lo[4], hi[4];
    #pragma unroll
    for (int c = 0; c < 4; c++) upk2(acc[c], lo[c], hi[c]);

    uint2* out2 = (uint2*)out;
    int rowA = rowBase + 2 * rp;
    __half2 a01 = __floats2half2_rn(lo[0], lo[1]);
    __half2 a23 = __floats2half2_rn(lo[2], lo[3]);
    __half2 b01 = __floats2half2_rn(hi[0], hi[1]);
    __half2 b23 = __floats2half2_rn(hi[2], hi[3]);
    uint2 va, vb;
    va.x = *(uint32_t*)&a01; va.y = *(uint32_t*)&a23;
    vb.x = *(uint32_t*)&b01; vb.y = *(uint32_t*)&b23;
    out2[rowA * 32 + cg]       = va;
    out2[(rowA + 1) * 32 + cg] = vb;
}

// -------- extract body: register-batched loads + integer tests -------------
__device__ __forceinline__ void extract_body(const float* __restrict__ A,
                                             int bid, int tid) {
    const uint4* A4 = (const uint4*)A;
    int base = bid * 2048 + tid;
    uint4 u[8];
    #pragma unroll
    for (int s = 0; s < 8; s++) u[s] = __ldcs(A4 + base + 256 * s);  // MLP=8
    #pragma unroll
    for (int s = 0; s < 8; s++) {
        if (u[s].x | u[s].y | u[s].z | u[s].w) {   // A is exactly 0.0f/1.0f
            int idx0 = (base + 256 * s) * 4;
            uint32_t w[4] = {u[s].x, u[s].y, u[s].z, u[s].w};
            #pragma unroll
            for (int c = 0; c < 4; c++) {
                if (w[c]) {
                    int idx = idx0 + c;
                    int i = idx & (N - 1);   // col = dst
                    int j = idx >> 13;       // row = src
                    int p = atomicAdd(&g_cnt[i], 1);
                    if (p < CSRW) g_csr[i * CSRW + p] = j;
                }
            }
        }
    }
}

// ------- fused: scalar gemm1 (blocks 0..511, FIRST) + extract --------------
__global__ void __launch_bounds__(256)
fused_extract_gemm_kernel(const float* __restrict__ A,
                          const float* __restrict__ X,
                          const float* __restrict__ W1,
                          __half* __restrict__ Z) {
    __shared__ float Xs[128 * XS_STRIDE];
    int b = blockIdx.x;
    if (b < GEMM_GRID) {
        gemm_body_h(X, W1, Z, b * GEMM_ROWS, threadIdx.x, Xs);
    } else {
        extract_body(A, b - GEMM_GRID, threadIdx.x);
    }
}

// -------- prep_pre: zero g_cnt + W2 -> fp16 (runs FIRST) -------------------
__global__ void __launch_bounds__(256)
prep_pre_kernel(const float* __restrict__ W2) {
    int b = blockIdx.x, tid = threadIdx.x;
    if (b < 16) {                    // W2: 4096 float4
        int q = b * 256 + tid;
        float4 v = ((const float4*)W2)[q];
        __half2 h01 = __floats2half2_rn(v.x, v.y);
        __half2 h23 = __floats2half2_rn(v.z, v.w);
        uint2 u;
        u.x = *(uint32_t*)&h01; u.y = *(uint32_t*)&h23;
        ((uint2*)g_W2h)[q] = u;
    } else {                         // zero g_cnt: 2048 int4
        ((int4*)g_cnt)[(b - 16) * 256 + tid] = make_int4(0, 0, 0, 0);
    }
}

// ---- dis_scale: build g_dis AND scale layer-1 Z in place by dis_row -------
__global__ void __launch_bounds__(256)
dis_scale_kernel() {
    int q = blockIdx.x * 256 + threadIdx.x;  // grid 512: 131072 uint4 (8 halves)
    int r = q >> 4;                          // row (16 uint4 per row)
    float d = rsqrtf((float)g_cnt[r] + 1.0f);
    if ((q & 15) == 0) g_dis[r] = d;
    uint4 v = ((const uint4*)g_Z)[q];
    uint32_t* h = (uint32_t*)&v;
    #pragma unroll
    for (int j = 0; j < 4; j++) {
        float2 f = __half22float2(*(const __half2*)&h[j]);
        __half2 s = __floats2half2_rn(f.x * d, f.y * d);
        h[j] = *(uint32_t*)&s;
    }
    ((uint4*)g_Z)[q] = v;
}

// -------- HMMA gemm2: grid 512, 128 thr, block tile 16x128, warp 16x32 -----
// Epilogue scales by g_dis[row] (Z must be dis-scaled for spmm2).
__global__ void __launch_bounds__(128)
hgemm_kernel(const __half* __restrict__ Ag,   // [N,128] fp16
             __half* __restrict__ outg) {     // [N,128] fp16, dis-scaled
    __shared__ __align__(16) __half As[16 * BP];
    __shared__ __align__(16) __half Bs[128 * BP];
    int tid = threadIdx.x;
    int rowBase = blockIdx.x * 16;

    const uint4* A4 = (const uint4*)(Ag + rowBase * F);
    #pragma unroll
    for (int it = 0; it < 2; it++) {
        int idx = tid + 128 * it;
        int r = idx >> 4, c8 = idx & 15;
        *(uint4*)&As[r * BP + c8 * 8] = A4[idx];
    }
    const uint4* B4 = (const uint4*)g_W2h;
    #pragma unroll
    for (int it = 0; it < 16; it++) {
        int idx = tid + 128 * it;
        int r = idx >> 4, c8 = idx & 15;
        *(uint4*)&Bs[r * BP + c8 * 8] = B4[idx];
    }
    __syncthreads();

    int warp = tid >> 5, lane = tid & 31;
    int n0 = warp * 32;

    float c[4][4];
    #pragma unroll
    for (int nb = 0; nb < 4; nb++)
        #pragma unroll
        for (int q = 0; q < 4; q++) c[nb][q] = 0.0f;

    unsigned aBase = (unsigned)__cvta_generic_to_shared(As);
    unsigned bBase = (unsigned)__cvta_generic_to_shared(Bs);
    int lr = lane & 15, lc = lane >> 4;

    #pragma unroll
    for (int kc = 0; kc < 8; kc++) {
        uint32_t a[4];
        {
            unsigned addr = aBase + ((lr * BP + kc * 16 + lc * 8) << 1);
            asm volatile("ldmatrix.sync.aligned.m8n8.x4.shared.b16 {%0,%1,%2,%3}, [%4];"
                         : "=r"(a[0]), "=r"(a[1]), "=r"(a[2]), "=r"(a[3])
                         : "r"(addr));
        }
        uint32_t b[2][4];
        #pragma unroll
        for (int nt = 0; nt < 2; nt++) {
            unsigned addr = bBase + (((kc * 16 + lr) * BP + n0 + nt * 16 + lc * 8) << 1);
            asm volatile("ldmatrix.sync.aligned.m8n8.x4.trans.shared.b16 {%0,%1,%2,%3}, [%4];"
                         : "=r"(b[nt][0]), "=r"(b[nt][1]), "=r"(b[nt][2]), "=r"(b[nt][3])
                         : "r"(addr));
        }
        #pragma unroll
        for (int nb = 0; nb < 4; nb++) {
            uint32_t b0 = b[nb >> 1][(nb & 1) * 2];
            uint32_t b1 = b[nb >> 1][(nb & 1) * 2 + 1];
            asm volatile(
                "mma.sync.aligned.m16n8k16.row.col.f32.f16.f16.f32 "
                "{%0,%1,%2,%3}, {%4,%5,%6,%7}, {%8,%9}, {%0,%1,%2,%3};"
                : "+f"(c[nb][0]), "+f"(c[nb][1]), "+f"(c[nb][2]), "+f"(c[nb][3])
                : "r"(a[0]), "r"(a[1]), "r"(a[2]), "r"(a[3]),
                  "r"(b0), "r"(b1));
        }
    }

    __half2* O2 = (__half2*)outg;
    int fr = lane >> 2, fc = lane & 3;
    int row0 = rowBase + fr;
    int row1 = row0 + 8;
    float d0 = g_dis[row0];
    float d1 = g_dis[row1];
    #pragma unroll
    for (int nb = 0; nb < 4; nb++) {
        int col2 = (n0 + nb * 8 + 2 * fc) >> 1;
        O2[row0 * 64 + col2] = __floats2half2_rn(c[nb][0] * d0, c[nb][1] * d0);
        O2[row1 * 64 + col2] = __floats2half2_rn(c[nb][2] * d1, c[nb][3] * d1);
    }
}

// ---- SpMM v6: one warp per dst row; fp16 tree-sum per 8-edge batch --------
// Z pre-scaled by dis_j. out[i,:] = relu(dis_i*(Zs[i,:]+sum Zs[j,:]) + b)
#define H2(x) (*(const __half2*)&(x))
template<bool HOUT>
__global__ void __launch_bounds__(256)
spmm_kernel(const __half* __restrict__ Z,
            const float* __restrict__ bias,
            void* __restrict__ outv) {
    __shared__ int sidx[8][CSRW];
    int warp = threadIdx.x >> 5;
    int lane = threadIdx.x & 31;
    int i = blockIdx.x * 8 + warp;

    int cnt = g_cnt[i];
    int m = cnt < CSRW ? cnt : CSRW;

    for (int e = lane; e < m; e += 32)
        sidx[warp][e] = g_csr[i * CSRW + e] * 32;
    __syncwarp();

    const uint2* Z2 = (const uint2*)Z;
    float dis_i = g_dis[i];

    uint2 self = Z2[i * 32 + lane];   // already dis_i-scaled
    float2 sa = __half22float2(H2(self.x));
    float2 sb = __half22float2(H2(self.y));
    uint64_t acc0 = pk2(sa.x, sa.y);
    uint64_t acc1 = pk2(sb.x, sb.y);

    int e = 0;
    for (; e + 8 <= m; e += 8) {
        uint2 u[8];
        #pragma unroll
        for (int q = 0; q < 8; q++) u[q] = Z2[sidx[warp][e + q] + lane];
        // fp16 pairwise tree (3 levels) per component, then one fp32 add
        __half2 x0 = __hadd2(H2(u[0].x), H2(u[1].x));
        __half2 x1 = __hadd2(H2(u[2].x), H2(u[3].x));
        __half2 x2 = __hadd2(H2(u[4].x), H2(u[5].x));
        __half2 x3 = __hadd2(H2(u[6].x), H2(u[7].x));
        __half2 y0 = __hadd2(H2(u[0].y), H2(u[1].y));
        __half2 y1 = __hadd2(H2(u[2].y), H2(u[3].y));
        __half2 y2 = __hadd2(H2(u[4].y), H2(u[5].y));
        __half2 y3 = __hadd2(H2(u[6].y), H2(u[7].y));
        x0 = __hadd2(x0, x1); x2 = __hadd2(x2, x3);
        y0 = __hadd2(y0, y1); y2 = __hadd2(y2, y3);
        x0 = __hadd2(x0, x2);
        y0 = __hadd2(y0, y2);
        float2 fx = __half22float2(x0);
        float2 fy = __half22float2(y0);
        acc0 = add2(acc0, pk2(fx.x, fx.y));
        acc1 = add2(acc1, pk2(fy.x, fy.y));
    }
    for (; e < m; e++) {              // remainder in fp32
        uint2 u = Z2[sidx[warp][e] + lane];
        float2 fa = __half22float2(H2(u.x));
        float2 fb = __half22float2(H2(u.y));
        acc0 = add2(acc0, pk2(fa.x, fa.y));
        acc1 = add2(acc1, pk2(fb.x, fb.y));
    }

    float a0, a1, a2, a3;
    upk2(acc0, a0, a1);
    upk2(acc1, a2, a3);
    float4 b4 = ((const float4*)bias)[lane];
    float r0 = fmaxf(dis_i * a0 + b4.x, 0.0f);
    float r1 = fmaxf(dis_i * a1 + b4.y, 0.0f);
    float r2 = fmaxf(dis_i * a2 + b4.z, 0.0f);
    float r3 = fmaxf(dis_i * a3 + b4.w, 0.0f);

    if (HOUT) {
        __half2 h01 = __floats2half2_rn(r0, r1);
        __half2 h23 = __floats2half2_rn(r2, r3);
        uint2 v;
        v.x = *(uint32_t*)&h01; v.y = *(uint32_t*)&h23;
        ((uint2*)outv)[i * 32 + lane] = v;
    } else {
        ((float4*)outv)[i * 32 + lane] = make_float4(r0, r1, r2, r3);
    }
}

// ---------------- launch ---------------------------------------------------
extern "C" void kernel_launch(void* const* d_in, const int* in_sizes, int n_in,
                              void* d_out, int out_size) {
    const float* X  = (const float*)d_in[0];
    const float* A  = (const float*)d_in[1];
    const float* W1 = (const float*)d_in[2];
    const float* b1 = (const float*)d_in[3];
    const float* W2 = (const float*)d_in[4];
    const float* b2 = (const float*)d_in[5];
    float* out = (float*)d_out;

    __half* Z;  cudaGetSymbolAddress((void**)&Z,  g_Z);
    __half* H1; cudaGetSymbolAddress((void**)&H1, g_H1);

    prep_pre_kernel<<<24, 256>>>(W2);               // zero cnt + W2 fp16

    // scalar gemm1 (blocks 0..511, start immediately) + extract CSR (8192 blocks)
    fused_extract_gemm_kernel<<<GEMM_GRID + 8192, 256>>>(A, X, W1, Z);
    dis_scale_kernel<<<512, 256>>>();               // g_dis + Z *= dis_row

    spmm_kernel<true ><<<1024, 256>>>(Z, b1, H1);   // H1 = relu(An@(X@W1)+b1), fp16
    hgemm_kernel<<<512, 128>>>(H1, Z);              // Z = dis .* (H1 @ W2)  (HMMA)
    spmm_kernel<false><<<1024, 256>>>(Z, b2, out);  // out = relu(An@(H1@W2)+b2)
}